// round 17
// baseline (speedup 1.0000x reference)
#include <cuda_runtime.h>
#include <cuda_fp16.h>
#include <cstdint>

#define T_STEPS 50
#define BATCH   128
#define NIN     16384
#define NH      256
#define NO      11
#define M_TOT   (T_STEPS * BATCH)     // 6400

#define BM      64
#define BN      128
#define CHUNKS  (NIN / 32)            // 512
#define KSPLIT  3
#define CPK     171                   // 171+171+170
#define EPS     1.2e-2f

#define XSS     68                    // Xs row stride (u32): 64 + 4 pad
#define WSS     132                   // Ws row stride (u32): 128 + 4 pad

// ---------------------------------------------------------------------------
// Device scratch
// ---------------------------------------------------------------------------
__device__ float  g_part[(size_t)KSPLIT * M_TOT * NH];
__device__ float  g_cur1[(size_t)M_TOT * NH];
__device__ float  g_spk1[(size_t)M_TOT * NH];
__device__ float  g_cur2[(size_t)M_TOT * NO];
__device__ __half g_xh[(size_t)M_TOT * NIN];   // 210 MB
__device__ __half g_wh[(size_t)NH * NIN];      // 8.4 MB
__device__ int    g_flags[1 + BATCH * NH];

// ---------------------------------------------------------------------------
// Kernel 0a/0b: convert X / W1 to half (once, bandwidth-bound)
// ---------------------------------------------------------------------------
__global__ __launch_bounds__(256) void convh(const float* __restrict__ src,
                                             __half* __restrict__ dst) {
    const size_t gi = (size_t)blockIdx.x * 256 + threadIdx.x;
    float4 f = reinterpret_cast<const float4*>(src)[gi];
    __half2 h0 = __float22half2_rn(make_float2(f.x, f.y));
    __half2 h1 = __float22half2_rn(make_float2(f.z, f.w));
    uint2 v;
    v.x = *reinterpret_cast<uint32_t*>(&h0);
    v.y = *reinterpret_cast<uint32_t*>(&h1);
    reinterpret_cast<uint2*>(dst)[gi] = v;
}

// ---------------------------------------------------------------------------
// Kernel 1: partial[ks] = approx X @ W1^T via HFMA2 (packed half2 fma).
// k-pairs live in the two half lanes; flush to fp32 every 64 k.
// Tile 64x128, 256 threads (8 warps 2M x 4N), thread tile 8x4.
// grid (2, 100, 3).
// ---------------------------------------------------------------------------
__global__ __launch_bounds__(256, 2) void gemm_h2(
    const __half* __restrict__ xh,
    const __half* __restrict__ wh,
    float* __restrict__ part)
{
    __shared__ uint32_t Xs[16 * XSS];   // [kpair][row]
    __shared__ uint32_t Ws[16 * WSS];   // [kpair][col]

    const int tid  = threadIdx.x;
    const int wid  = tid >> 5;
    const int lane = tid & 31;
    const int n0 = blockIdx.x * BN;
    const int m0 = blockIdx.y * BM;
    const int c0 = blockIdx.z * CPK;
    const int nch = min(CHUNKS - c0, CPK);
    const int warpM = wid & 1;
    const int warpN = wid >> 1;
    const int lm = lane >> 3;           // 0..3 -> 8 rows each
    const int ln = lane & 7;            // 0..7 -> 4 cols each
    const int r0 = warpM * 32 + lm * 8;
    const int cb = warpN * 32 + ln * 4;

    // X producer: row tid>>2, 8 halfs (4 pairs) at pair offset (tid&3)*4
    const int xrow = tid >> 2;
    const int xkp  = (tid & 3) * 4;
    const __half* xp = xh + (size_t)(m0 + xrow) * NIN + (size_t)c0 * 32 + xkp * 2;

    // W producer: row tid>>1, 16 halfs (8 pairs) at pair offset (tid&1)*8
    const int wrow = tid >> 1;
    const int wkp  = (tid & 1) * 8;
    const __half* wp = wh + (size_t)(n0 + wrow) * NIN + (size_t)c0 * 32 + wkp * 2;

    __half2 acc[8][4];
    float   sum[8][4];
    const __half2 hz = __float2half2_rn(0.0f);
#pragma unroll
    for (int i = 0; i < 8; i++)
#pragma unroll
        for (int j = 0; j < 4; j++) { acc[i][j] = hz; sum[i][j] = 0.0f; }

    // prefetch chunk 0
    uint4 xv = *reinterpret_cast<const uint4*>(xp);
    uint4 wv0 = *reinterpret_cast<const uint4*>(wp);
    uint4 wv1 = *reinterpret_cast<const uint4*>(wp + 8);

    for (int c = 0; c < nch; c++) {
        __syncthreads();                 // previous compute done

        // stage X(c): 4 pairs
        Xs[(xkp + 0) * XSS + xrow] = xv.x;
        Xs[(xkp + 1) * XSS + xrow] = xv.y;
        Xs[(xkp + 2) * XSS + xrow] = xv.z;
        Xs[(xkp + 3) * XSS + xrow] = xv.w;
        // stage W(c): 8 pairs
        Ws[(wkp + 0) * WSS + wrow] = wv0.x;
        Ws[(wkp + 1) * WSS + wrow] = wv0.y;
        Ws[(wkp + 2) * WSS + wrow] = wv0.z;
        Ws[(wkp + 3) * WSS + wrow] = wv0.w;
        Ws[(wkp + 4) * WSS + wrow] = wv1.x;
        Ws[(wkp + 5) * WSS + wrow] = wv1.y;
        Ws[(wkp + 6) * WSS + wrow] = wv1.z;
        Ws[(wkp + 7) * WSS + wrow] = wv1.w;

        // prefetch chunk c+1
        if (c + 1 < nch) {
            const __half* xn = xp + (size_t)(c + 1) * 32;
            const __half* wn = wp + (size_t)(c + 1) * 32;
            xv  = *reinterpret_cast<const uint4*>(xn);
            wv0 = *reinterpret_cast<const uint4*>(wn);
            wv1 = *reinterpret_cast<const uint4*>(wn + 8);
        }

        __syncthreads();                 // tiles visible

        // compute: 16 k-pairs x (8m x 4n) HFMA2
#pragma unroll
        for (int kp = 0; kp < 16; kp++) {
            uint4 Aa = *reinterpret_cast<const uint4*>(&Xs[kp * XSS + r0]);
            uint4 Ab = *reinterpret_cast<const uint4*>(&Xs[kp * XSS + r0 + 4]);
            uint4 Bv = *reinterpret_cast<const uint4*>(&Ws[kp * WSS + cb]);
            __half2 a[8], b[4];
            a[0] = *reinterpret_cast<__half2*>(&Aa.x);
            a[1] = *reinterpret_cast<__half2*>(&Aa.y);
            a[2] = *reinterpret_cast<__half2*>(&Aa.z);
            a[3] = *reinterpret_cast<__half2*>(&Aa.w);
            a[4] = *reinterpret_cast<__half2*>(&Ab.x);
            a[5] = *reinterpret_cast<__half2*>(&Ab.y);
            a[6] = *reinterpret_cast<__half2*>(&Ab.z);
            a[7] = *reinterpret_cast<__half2*>(&Ab.w);
            b[0] = *reinterpret_cast<__half2*>(&Bv.x);
            b[1] = *reinterpret_cast<__half2*>(&Bv.y);
            b[2] = *reinterpret_cast<__half2*>(&Bv.z);
            b[3] = *reinterpret_cast<__half2*>(&Bv.w);
#pragma unroll
            for (int i = 0; i < 8; i++)
#pragma unroll
                for (int j = 0; j < 4; j++)
                    acc[i][j] = __hfma2(a[i], b[j], acc[i][j]);
        }

        // flush to fp32 every 2 chunks (64 k) and at the end
        if ((c & 1) == 1 || c == nch - 1) {
#pragma unroll
            for (int i = 0; i < 8; i++)
#pragma unroll
                for (int j = 0; j < 4; j++) {
                    float2 f = __half22float2(acc[i][j]);
                    sum[i][j] += (f.x + f.y);
                    acc[i][j] = hz;
                }
        }
    }

    // epilogue: raw partial sums
    float* po = part + (size_t)blockIdx.z * M_TOT * NH;
#pragma unroll
    for (int i = 0; i < 8; i++) {
        const int row = m0 + r0 + i;
        float4 v;
        v.x = sum[i][0];
        v.y = sum[i][1];
        v.z = sum[i][2];
        v.w = sum[i][3];
        *reinterpret_cast<float4*>(po + (size_t)row * NH + n0 + cb) = v;
    }
}

// ---------------------------------------------------------------------------
// Kernel 2: reduce 3 partials + bias -> cur1; flag near-threshold chains
// ---------------------------------------------------------------------------
__global__ __launch_bounds__(256) void reduce_flag(
    const float* __restrict__ part,
    const float* __restrict__ b1,
    float* __restrict__ cur1,
    int* __restrict__ flags)
{
    const int b = blockIdx.x, j = threadIdx.x;
    const float bias = b1[j];
    const size_t P = (size_t)M_TOT * NH;
    const size_t base = (size_t)b * NH + j;
    const size_t ts = (size_t)BATCH * NH;

    float mem = 0.0f;
    bool risky = false;
#pragma unroll 5
    for (int t = 0; t < T_STEPS; t++) {
        const size_t idx = base + (size_t)t * ts;
        const float c = ((part[idx] + part[idx + P]) + part[idx + 2 * P]) + bias;
        cur1[idx] = c;
        mem = 0.9f * mem + c;
        const float d = mem - 1.0f;
        risky |= (fabsf(d) < EPS);
        mem -= (d > 0.0f) ? 1.0f : 0.0f;
    }
    if (risky) {
        const int pos = atomicAdd(&flags[0], 1);
        flags[1 + pos] = (b << 8) | j;
    }
}

// ---------------------------------------------------------------------------
// Kernel 3: bitwise-R1 repair of flagged chains (proven R12/13/15/16)
// ---------------------------------------------------------------------------
__global__ __launch_bounds__(256) void fix2(
    const float* __restrict__ X,
    const float* __restrict__ W1,
    const float* __restrict__ b1,
    float* __restrict__ cur1,
    const int* __restrict__ flags)
{
    const int total = flags[0] * T_STEPS;
    for (int idx = blockIdx.x * blockDim.x + threadIdx.x; idx < total;
         idx += gridDim.x * blockDim.x) {
        const int ci = idx / T_STEPS;
        const int t  = idx - ci * T_STEPS;
        const int bj = flags[1 + ci];
        const int b = bj >> 8, j = bj & (NH - 1);
        const float* xr = X + ((size_t)t * BATCH + b) * NIN;
        const float* wr = W1 + (size_t)j * NIN;
        float acc = 0.0f;
        for (int k = 0; k < NIN; k += 8) {
            float4 x0 = *reinterpret_cast<const float4*>(xr + k);
            float4 x1 = *reinterpret_cast<const float4*>(xr + k + 4);
            float4 w0 = *reinterpret_cast<const float4*>(wr + k);
            float4 w1 = *reinterpret_cast<const float4*>(wr + k + 4);
            acc = fmaf(x0.x, w0.x, acc);
            acc = fmaf(x0.y, w0.y, acc);
            acc = fmaf(x0.z, w0.z, acc);
            acc = fmaf(x0.w, w0.w, acc);
            acc = fmaf(x1.x, w1.x, acc);
            acc = fmaf(x1.y, w1.y, acc);
            acc = fmaf(x1.z, w1.z, acc);
            acc = fmaf(x1.w, w1.w, acc);
        }
        cur1[((size_t)t * BATCH + b) * NH + j] = acc + b1[j];
    }
}

// ---------------------------------------------------------------------------
// Kernels 4-6: VERBATIM round-14 split scan path (proven bitwise)
// ---------------------------------------------------------------------------
__global__ __launch_bounds__(256) void scan1(const float* __restrict__ cur1,
                                             float* __restrict__ spk1) {
    const int b = blockIdx.x, j = threadIdx.x;
    float mem1 = 0.0f;
#pragma unroll 5
    for (int t = 0; t < T_STEPS; t++) {
        const float c1 = cur1[((size_t)t * BATCH + b) * NH + j];
        mem1 = 0.9f * mem1 + c1;
        const float spk = (mem1 - 1.0f > 0.0f) ? 1.0f : 0.0f;
        mem1 -= spk;
        spk1[((size_t)t * BATCH + b) * NH + j] = spk;
    }
}

__global__ __launch_bounds__(256) void layer2k(const float* __restrict__ spk1,
                                               const float* __restrict__ W2,
                                               const float* __restrict__ b2,
                                               float* __restrict__ cur2) {
    const int w8  = threadIdx.x >> 5;
    const int lid = threadIdx.x & 31;
    const int tb  = blockIdx.x * 8 + w8;

    float acc[NO];
#pragma unroll
    for (int o = 0; o < NO; o++) acc[o] = b2[o];

    const float* srow = spk1 + (size_t)tb * NH;

#pragma unroll
    for (int w = 0; w < 8; w++) {
        const float s = srow[w * 32 + lid];
        float p[NO];
#pragma unroll
        for (int o = 0; o < NO; o++) p[o] = s * W2[o * NH + w * 32 + lid];
#pragma unroll
        for (int o = 0; o < NO; o++) {
#pragma unroll
            for (int off = 16; off > 0; off >>= 1)
                p[o] += __shfl_xor_sync(0xFFFFFFFFu, p[o], off);
        }
#pragma unroll
        for (int o = 0; o < NO; o++) {
            const float q0 = __shfl_sync(0xFFFFFFFFu, p[o], 0);
            acc[o] += q0;
        }
    }

    if (lid < NO)
        cur2[(size_t)tb * NO + lid] = acc[lid];
}

__global__ __launch_bounds__(256) void scan2(const float* __restrict__ cur2,
                                             float* __restrict__ out) {
    const int gid = blockIdx.x * 256 + threadIdx.x;
    if (gid >= BATCH * NO) return;
    float mem2 = 0.0f;
#pragma unroll 5
    for (int t = 0; t < T_STEPS; t++) {
        const float c2 = cur2[(size_t)t * BATCH * NO + gid];
        mem2 = 0.9f * mem2 + c2;
        const float spk = (mem2 - 1.0f > 0.0f) ? 1.0f : 0.0f;
        mem2 -= spk;
        out[(size_t)t * BATCH * NO + gid] = spk;
    }
}

// ---------------------------------------------------------------------------
extern "C" void kernel_launch(void* const* d_in, const int* in_sizes, int n_in,
                              void* d_out, int out_size)
{
    const float* x  = (const float*)d_in[0];
    const float* W1 = (const float*)d_in[1];
    const float* b1 = (const float*)d_in[2];
    const float* W2 = (const float*)d_in[3];
    const float* b2 = (const float*)d_in[4];
    float* out = (float*)d_out;

    float *partp, *cur1, *spk1, *cur2;
    __half *xhp, *whp;
    int* flagsp;
    cudaGetSymbolAddress((void**)&partp, g_part);
    cudaGetSymbolAddress((void**)&cur1, g_cur1);
    cudaGetSymbolAddress((void**)&spk1, g_spk1);
    cudaGetSymbolAddress((void**)&cur2, g_cur2);
    cudaGetSymbolAddress((void**)&xhp, g_xh);
    cudaGetSymbolAddress((void**)&whp, g_wh);
    cudaGetSymbolAddress((void**)&flagsp, g_flags);

    cudaMemsetAsync(flagsp, 0, sizeof(int));
    convh<<<(int)((size_t)NH * NIN / 4 / 256), 256>>>(W1, whp);
    convh<<<(int)((size_t)M_TOT * NIN / 4 / 256), 256>>>(x, xhp);
    gemm_h2<<<dim3(2, 100, KSPLIT), 256>>>(xhp, whp, partp);
    reduce_flag<<<BATCH, NH>>>(partp, b1, cur1, flagsp);
    fix2<<<592, 256>>>(x, W1, b1, cur1, flagsp);
    scan1<<<BATCH, NH>>>(cur1, spk1);
    layer2k<<<M_TOT / 8, 256>>>(spk1, W2, b2, cur2);
    scan2<<<(BATCH * NO + 255) / 256, 256>>>(cur2, out);
}